// round 1
// baseline (speedup 1.0000x reference)
#include <cuda_runtime.h>
#include <cub/cub.cuh>
#include <cstdint>

#define Bn 16384
#define Fn 512
#define Pn 128
#define NTOT (Bn * Pn)            // 2,097,152
#define NBLK_DELTA (NTOT / 256)   // 8192

// ---------------- static device scratch (no runtime allocation) ----------------
__device__ float g_P[Fn * Pn];    // normalized projections [f][p]
__device__ float g_PT[Pn * Fn];   // transposed             [p][f]
__device__ unsigned long long g_srcKeys[NTOT];
__device__ unsigned long long g_srcKeysOut[NTOT];
__device__ unsigned long long g_tgtKeys[NTOT];
__device__ unsigned long long g_tgtKeysOut[NTOT];
__device__ float g_delta[Bn * Pn];          // [b][p]
__device__ float g_mv[(size_t)Bn * Fn];     // movement scratch [b][f]
__device__ float g_partials[NBLK_DELTA];
__device__ __align__(256) unsigned char g_temp[96u << 20];  // CUB temp storage

// ---------------- helpers ----------------
__device__ __forceinline__ unsigned int fflip(float f) {
    unsigned int u = __float_as_uint(f);
    return u ^ ((u >> 31) ? 0xFFFFFFFFu : 0x80000000u);
}
__device__ __forceinline__ float funflip(unsigned int u) {
    return __uint_as_float(u ^ ((u >> 31) ? 0x80000000u : 0xFFFFFFFFu));
}

// ---------------- kernel A: normalize projection columns ----------------
// 1 block, 128 threads: thread p owns column p (stride-Pn access is coalesced
// across threads since consecutive threads hit consecutive addresses).
__global__ void normalize_projs_kernel(const float* __restrict__ projs) {
    int p = threadIdx.x;
    float s = 0.f;
    for (int f = 0; f < Fn; ++f) {
        float v = projs[f * Pn + p];
        s += v * v;
    }
    float inv = 1.0f / sqrtf(s);
    for (int f = 0; f < Fn; ++f) {
        float w = projs[f * Pn + p] * inv;
        g_P[f * Pn + p] = w;
        g_PT[p * Fn + f] = w;
    }
}

// ---------------- kernel B: projection GEMM + key packing ----------------
// src_p[b][p] = sum_f A[b][f] * P[f][p];  grid.y selects src/tgt.
// BM=64, BN=128 (full), BK=32; 256 threads, 4x8 microtile per thread.
__global__ void proj_gemm_kernel(const float* __restrict__ src,
                                 const float* __restrict__ tgt) {
    const float* A = blockIdx.y ? tgt : src;
    unsigned long long* K = blockIdx.y ? g_tgtKeys : g_srcKeys;

    __shared__ float As[64][33];
    __shared__ float Bs[32][128];

    int tid = threadIdx.x;           // 256
    int b0 = blockIdx.x * 64;
    int ty = tid >> 4;               // 0..15 -> 4 b-rows each
    int tx = tid & 15;               // 0..15 -> 8 p-cols each

    float acc[4][8];
#pragma unroll
    for (int i = 0; i < 4; ++i)
#pragma unroll
        for (int j = 0; j < 8; ++j) acc[i][j] = 0.f;

    for (int k0 = 0; k0 < Fn; k0 += 32) {
        // load A tile 64x32
        for (int l = tid; l < 64 * 32; l += 256) {
            int r = l >> 5, c = l & 31;
            As[r][c] = A[(size_t)(b0 + r) * Fn + k0 + c];
        }
        // load B tile 32x128
        for (int l = tid; l < 32 * 128; l += 256) {
            int r = l >> 7, c = l & 127;
            Bs[r][c] = g_P[(k0 + r) * Pn + c];
        }
        __syncthreads();
#pragma unroll
        for (int k = 0; k < 32; ++k) {
            float a[4], bb[8];
#pragma unroll
            for (int i = 0; i < 4; ++i) a[i] = As[ty * 4 + i][k];
#pragma unroll
            for (int j = 0; j < 8; ++j) bb[j] = Bs[k][tx * 8 + j];
#pragma unroll
            for (int i = 0; i < 4; ++i)
#pragma unroll
                for (int j = 0; j < 8; ++j) acc[i][j] += a[i] * bb[j];
        }
        __syncthreads();
    }

#pragma unroll
    for (int i = 0; i < 4; ++i) {
        int b = b0 + ty * 4 + i;
#pragma unroll
        for (int j = 0; j < 8; ++j) {
            int p = tx * 8 + j;
            unsigned int u = fflip(acc[i][j]);
            unsigned long long key = ((unsigned long long)p << 46)
                                   | ((unsigned long long)u << 14)
                                   | (unsigned long long)b;
            K[(size_t)b * Pn + p] = key;
        }
    }
}

// ---------------- kernel D: delta computation + partial sums ----------------
__global__ void delta_kernel() {
    int j = blockIdx.x * 256 + threadIdx.x;
    unsigned long long sk = g_srcKeysOut[j];
    unsigned long long tk = g_tgtKeysOut[j];
    int b = (int)(sk & 0x3FFFull);
    int p = j >> 14;  // segments are contiguous, exactly 2^14 each
    float sv = funflip((unsigned int)((sk >> 14) & 0xFFFFFFFFull));
    float tv = funflip((unsigned int)((tk >> 14) & 0xFFFFFFFFull));
    float d = tv - sv;
    g_delta[b * Pn + p] = d;

    // deterministic per-block partial of d*d
    float s = d * d;
#pragma unroll
    for (int o = 16; o; o >>= 1) s += __shfl_xor_sync(0xFFFFFFFFu, s, o);
    __shared__ float ws[8];
    int lane = threadIdx.x & 31, wid = threadIdx.x >> 5;
    if (lane == 0) ws[wid] = s;
    __syncthreads();
    if (threadIdx.x == 0) {
        float t = 0.f;
#pragma unroll
        for (int w = 0; w < 8; ++w) t += ws[w];
        g_partials[blockIdx.x] = t;
    }
}

// ---------------- kernel E: movement GEMM ----------------
// mv[b][f] = sum_p delta[b][p] * PT[p][f].  BM=64, BN=64, BK=64 (2 chunks).
__global__ void mv_gemm_kernel() {
    __shared__ float As[64][65];
    __shared__ float Bs[64][65];

    int tid = threadIdx.x;          // 256
    int b0 = blockIdx.x * 64;
    int f0 = blockIdx.y * 64;
    int ty = tid >> 4;              // -> 4 b-rows
    int tx = tid & 15;              // -> 4 f-cols

    float acc[4][4];
#pragma unroll
    for (int i = 0; i < 4; ++i)
#pragma unroll
        for (int j = 0; j < 4; ++j) acc[i][j] = 0.f;

    for (int k0 = 0; k0 < Pn; k0 += 64) {
        for (int l = tid; l < 64 * 64; l += 256) {
            int r = l >> 6, c = l & 63;
            As[r][c] = g_delta[(size_t)(b0 + r) * Pn + k0 + c];
        }
        for (int l = tid; l < 64 * 64; l += 256) {
            int r = l >> 6, c = l & 63;
            Bs[r][c] = g_PT[(size_t)(k0 + r) * Fn + f0 + c];
        }
        __syncthreads();
#pragma unroll
        for (int k = 0; k < 64; ++k) {
            float a[4], bb[4];
#pragma unroll
            for (int i = 0; i < 4; ++i) a[i] = As[ty * 4 + i][k];
#pragma unroll
            for (int j = 0; j < 4; ++j) bb[j] = Bs[k][tx * 4 + j];
#pragma unroll
            for (int i = 0; i < 4; ++i)
#pragma unroll
                for (int j = 0; j < 4; ++j) acc[i][j] += a[i] * bb[j];
        }
        __syncthreads();
    }

#pragma unroll
    for (int i = 0; i < 4; ++i) {
        size_t b = b0 + ty * 4 + i;
#pragma unroll
        for (int j = 0; j < 4; ++j) {
            g_mv[b * Fn + f0 + tx * 4 + j] = acc[i][j];
        }
    }
}

// ---------------- kernel F: row-normalize + write output ----------------
__global__ void norm_out_kernel(float* __restrict__ out) {
    int gwarp = (blockIdx.x * blockDim.x + threadIdx.x) >> 5;  // row = b
    int lane = threadIdx.x & 31;
    const float* row = g_mv + (size_t)gwarp * Fn;

    float v[16];
    float s = 0.f;
#pragma unroll
    for (int k = 0; k < 16; ++k) {
        v[k] = row[k * 32 + lane];
        s += v[k] * v[k];
    }
#pragma unroll
    for (int o = 16; o; o >>= 1) s += __shfl_xor_sync(0xFFFFFFFFu, s, o);
    float inv = 1.0f / sqrtf(s);
    float* orow = out + (size_t)gwarp * Fn;
#pragma unroll
    for (int k = 0; k < 16; ++k) orow[k * 32 + lane] = v[k] * inv;
}

// ---------------- kernel G: deterministic dist reduction ----------------
__global__ void dist_kernel(float* __restrict__ out) {
    __shared__ float sm[1024];
    int tid = threadIdx.x;
    float s = 0.f;
    for (int j = tid; j < NBLK_DELTA; j += 1024) s += g_partials[j];
    sm[tid] = s;
    __syncthreads();
    for (int st = 512; st; st >>= 1) {
        if (tid < st) sm[tid] += sm[tid + st];
        __syncthreads();
    }
    if (tid == 0) out[0] = sm[0] * (1.0f / (float)NTOT);
}

// ---------------- launch ----------------
extern "C" void kernel_launch(void* const* d_in, const int* in_sizes, int n_in,
                              void* d_out, int out_size) {
    const float* src   = (const float*)d_in[0];
    const float* tgt   = (const float*)d_in[1];
    const float* projs = (const float*)d_in[2];
    float* out = (float*)d_out;

    void *pSrcK, *pSrcKO, *pTgtK, *pTgtKO, *pTemp;
    cudaGetSymbolAddress(&pSrcK,  g_srcKeys);
    cudaGetSymbolAddress(&pSrcKO, g_srcKeysOut);
    cudaGetSymbolAddress(&pTgtK,  g_tgtKeys);
    cudaGetSymbolAddress(&pTgtKO, g_tgtKeysOut);
    cudaGetSymbolAddress(&pTemp,  g_temp);

    normalize_projs_kernel<<<1, 128>>>(projs);

    dim3 gb(Bn / 64, 2);
    proj_gemm_kernel<<<gb, 256>>>(src, tgt);

    size_t need = 0;
    cub::DeviceRadixSort::SortKeys(nullptr, need,
        (const unsigned long long*)pSrcK, (unsigned long long*)pSrcKO,
        NTOT, 0, 53);
    if (need > sizeof(g_temp)) need = sizeof(g_temp);  // defensive (96MB is ample)
    cub::DeviceRadixSort::SortKeys(pTemp, need,
        (const unsigned long long*)pSrcK, (unsigned long long*)pSrcKO,
        NTOT, 0, 53);
    cub::DeviceRadixSort::SortKeys(pTemp, need,
        (const unsigned long long*)pTgtK, (unsigned long long*)pTgtKO,
        NTOT, 0, 53);

    delta_kernel<<<NBLK_DELTA, 256>>>();

    dim3 gm(Bn / 64, Fn / 64);
    mv_gemm_kernel<<<gm, 256>>>();

    bool has_dist = (out_size != Bn * Fn);   // B*F+1 (or 1) -> dist present
    float* mv_out = has_dist ? out + 1 : out;

    if (out_size >= Bn * Fn) {
        norm_out_kernel<<<(Bn * 32) / 256, 256>>>(mv_out);
    }
    if (has_dist) {
        dist_kernel<<<1, 1024>>>(out);
    }
}

// round 2
// speedup vs baseline: 1.6534x; 1.6534x over previous
#include <cuda_runtime.h>
#include <cub/cub.cuh>
#include <cstdint>

#define Bn 16384
#define Fn 512
#define Pn 128
#define NTOT (Bn * Pn)            // 2,097,152
#define NTOT2 (2 * NTOT)          // 4,194,304 (src+tgt combined)
#define NBLK_DELTA (NTOT / 256)   // 8192

// ---------------- static device scratch (no runtime allocation) ----------------
__device__ __align__(128) float g_P[Fn * Pn];    // normalized projections [f][p]
__device__ __align__(128) float g_PT[Pn * Fn];   // transposed             [p][f]
__device__ __align__(128) unsigned long long g_keys[NTOT2];
__device__ __align__(128) unsigned long long g_keysOut[NTOT2];
__device__ __align__(128) unsigned short g_vals[NTOT2];
__device__ __align__(128) unsigned short g_valsOut[NTOT2];
__device__ __align__(128) float g_delta[Bn * Pn];          // [b][p]
__device__ float g_partials[NBLK_DELTA];
__device__ __align__(256) unsigned char g_temp[64u << 20];  // CUB temp storage

// ---------------- helpers ----------------
__device__ __forceinline__ unsigned int fflip(float f) {
    unsigned int u = __float_as_uint(f);
    return u ^ ((u >> 31) ? 0xFFFFFFFFu : 0x80000000u);
}
__device__ __forceinline__ float funflip(unsigned int u) {
    return __uint_as_float(u ^ ((u >> 31) ? 0x80000000u : 0xFFFFFFFFu));
}

// ---------------- kernel A: normalize projection columns ----------------
// IDENTICAL to round 1 (bitwise-stable P values; sort ranks depend on them).
__global__ void normalize_projs_kernel(const float* __restrict__ projs) {
    int p = threadIdx.x;
    float s = 0.f;
    for (int f = 0; f < Fn; ++f) {
        float v = projs[f * Pn + p];
        s += v * v;
    }
    float inv = 1.0f / sqrtf(s);
    for (int f = 0; f < Fn; ++f) {
        float w = projs[f * Pn + p] * inv;
        g_P[f * Pn + p] = w;
        g_PT[p * Fn + f] = w;
    }
}

// ---------------- kernel B: projection GEMM + fused key/payload packing ----
// Computes X @ P for X in {src, tgt} (grid.y), 128x128 tile, 8x8 microtile,
// k accumulated sequentially 0..511 (same FMA order as round 1 -> bitwise
// stable ranks). Epilogue transposes through smem and writes sort keys
// (40-bit: [val32 | p7 | t1]) and u16 payload (=b) fully coalesced.
__global__ __launch_bounds__(256, 2) void proj_gemm_kernel(
    const float* __restrict__ src, const float* __restrict__ tgt) {
    extern __shared__ float sm[];
    float* As = sm;                  // [16][132] transposed: [k][b]
    float* Bs = sm + 16 * 132;       // [16][132] : [k][p]
    float* Ts = sm + 2 * 16 * 132;   // [128][129]: [p][b]  (epilogue staging)

    const int t = blockIdx.y;
    const float* A = t ? tgt : src;
    const int b0 = blockIdx.x * 128;
    const int tid = threadIdx.x;
    const int ty = tid >> 4;   // 0..15
    const int tx = tid & 15;   // 0..15

    float acc[8][8];
#pragma unroll
    for (int i = 0; i < 8; ++i)
#pragma unroll
        for (int j = 0; j < 8; ++j) acc[i][j] = 0.f;

    for (int k0 = 0; k0 < Fn; k0 += 16) {
        // A tile 128x16, transposed into As[k][b]
#pragma unroll
        for (int it = 0; it < 2; ++it) {
            int idx = tid + it * 256;
            int r = idx >> 2, c4 = (idx & 3) * 4;
            float4 v = *(const float4*)&A[(size_t)(b0 + r) * Fn + k0 + c4];
            As[(c4 + 0) * 132 + r] = v.x;
            As[(c4 + 1) * 132 + r] = v.y;
            As[(c4 + 2) * 132 + r] = v.z;
            As[(c4 + 3) * 132 + r] = v.w;
        }
        // B tile 16x128
#pragma unroll
        for (int it = 0; it < 2; ++it) {
            int idx = tid + it * 256;
            int r = idx >> 5, c4 = (idx & 31) * 4;
            *(float4*)&Bs[r * 132 + c4] = *(const float4*)&g_P[(k0 + r) * Pn + c4];
        }
        __syncthreads();
#pragma unroll
        for (int k = 0; k < 16; ++k) {
            float a[8], b[8];
            *(float4*)&a[0] = *(float4*)&As[k * 132 + ty * 4];
            *(float4*)&a[4] = *(float4*)&As[k * 132 + 64 + ty * 4];
            *(float4*)&b[0] = *(float4*)&Bs[k * 132 + tx * 4];
            *(float4*)&b[4] = *(float4*)&Bs[k * 132 + 64 + tx * 4];
#pragma unroll
            for (int i = 0; i < 8; ++i)
#pragma unroll
                for (int j = 0; j < 8; ++j)
                    acc[i][j] = fmaf(a[i], b[j], acc[i][j]);
        }
        __syncthreads();
    }

    // stage to Ts[p][b]
#pragma unroll
    for (int i = 0; i < 8; ++i) {
        int r = (i < 4) ? (ty * 4 + i) : (64 + ty * 4 + (i - 4));
#pragma unroll
        for (int j = 0; j < 8; ++j) {
            int c = (j < 4) ? (tx * 4 + j) : (64 + tx * 4 + (j - 4));
            Ts[c * 129 + r] = acc[i][j];
        }
    }
    __syncthreads();

    // write keys + payloads: thread -> (p = tid>>1, 64 consecutive b)
    const int p = tid >> 1;
    const int half = (tid & 1) * 64;
    const unsigned seg = (unsigned)((t << 7) | p);
    const size_t base = ((size_t)seg << 14) | (unsigned)(b0 + half);
    const unsigned long long hi = (unsigned long long)seg << 32;
#pragma unroll 4
    for (int i = 0; i < 64; ++i) {
        unsigned u = fflip(Ts[p * 129 + half + i]);
        g_keys[base + i] = hi | u;
        g_vals[base + i] = (unsigned short)(b0 + half + i);
    }
}

// ---------------- kernel D: delta computation + partial sums ----------------
// (same reduction structure as round 1 -> bitwise-stable dist)
__global__ void delta_kernel() {
    int j = blockIdx.x * 256 + threadIdx.x;
    unsigned long long sk = g_keysOut[j];          // src half (t=0)
    unsigned long long tk = g_keysOut[j + NTOT];   // tgt half (t=1)
    int b = (int)g_valsOut[j];
    int p = j >> 14;  // 2^14 entries per (t,p) segment, contiguous
    float sv = funflip((unsigned int)(sk & 0xFFFFFFFFull));
    float tv = funflip((unsigned int)(tk & 0xFFFFFFFFull));
    float d = tv - sv;
    g_delta[b * Pn + p] = d;

    float s = d * d;
#pragma unroll
    for (int o = 16; o; o >>= 1) s += __shfl_xor_sync(0xFFFFFFFFu, s, o);
    __shared__ float ws[8];
    int lane = threadIdx.x & 31, wid = threadIdx.x >> 5;
    if (lane == 0) ws[wid] = s;
    __syncthreads();
    if (threadIdx.x == 0) {
        float t = 0.f;
#pragma unroll
        for (int w = 0; w < 8; ++w) t += ws[w];
        g_partials[blockIdx.x] = t;
    }
}

// ---------------- kernel E: movement GEMM fused with row-normalize ---------
// mv[b][f] = sum_p delta[b][p] * PT[p][f]; BM=32, BN=512 (full row per block)
// so the row L2-norm and final write happen in-block (no g_mv round trip).
__global__ __launch_bounds__(256, 2) void mv_norm_kernel(float* __restrict__ out) {
    extern __shared__ float sm[];
    float* As   = sm;                    // [32][36]   : [k][b]
    float* Bs   = sm + 32 * 36;          // [32][516]  : [k][f]
    float* part = Bs + 32 * 516;         // [32][65]
    float* inv  = part + 32 * 65;        // [32]

    const int b0 = blockIdx.x * 32;
    const int tid = threadIdx.x;
    const int ty = tid >> 6;   // 0..3
    const int tx = tid & 63;   // 0..63

    float acc[8][8];
#pragma unroll
    for (int i = 0; i < 8; ++i)
#pragma unroll
        for (int j = 0; j < 8; ++j) acc[i][j] = 0.f;

    for (int k0 = 0; k0 < Pn; k0 += 32) {
        {   // A tile 32x32, transposed
            int r = tid >> 3, c4 = (tid & 7) * 4;
            float4 v = *(const float4*)&g_delta[(size_t)(b0 + r) * Pn + k0 + c4];
            As[(c4 + 0) * 36 + r] = v.x;
            As[(c4 + 1) * 36 + r] = v.y;
            As[(c4 + 2) * 36 + r] = v.z;
            As[(c4 + 3) * 36 + r] = v.w;
        }
        // B tile 32x512
#pragma unroll
        for (int it = 0; it < 16; ++it) {
            int idx = tid + it * 256;
            int r = idx >> 7, c4 = (idx & 127) * 4;
            *(float4*)&Bs[r * 516 + c4] = *(const float4*)&g_PT[(size_t)(k0 + r) * Fn + c4];
        }
        __syncthreads();
#pragma unroll
        for (int k = 0; k < 32; ++k) {
            float a[8], b[8];
            *(float4*)&a[0] = *(float4*)&As[k * 36 + ty * 4];
            *(float4*)&a[4] = *(float4*)&As[k * 36 + 16 + ty * 4];
            *(float4*)&b[0] = *(float4*)&Bs[k * 516 + tx * 4];
            *(float4*)&b[4] = *(float4*)&Bs[k * 516 + 256 + tx * 4];
#pragma unroll
            for (int i = 0; i < 8; ++i)
#pragma unroll
                for (int j = 0; j < 8; ++j)
                    acc[i][j] = fmaf(a[i], b[j], acc[i][j]);
        }
        __syncthreads();
    }

    // per-row sum of squares
#pragma unroll
    for (int i = 0; i < 8; ++i) {
        int r = (i < 4) ? (ty * 4 + i) : (16 + ty * 4 + (i - 4));
        float s = 0.f;
#pragma unroll
        for (int j = 0; j < 8; ++j) s += acc[i][j] * acc[i][j];
        part[r * 65 + tx] = s;
    }
    __syncthreads();
    if (tid < 32) {
        float s = 0.f;
        for (int x = 0; x < 64; ++x) s += part[tid * 65 + x];
        inv[tid] = 1.0f / sqrtf(s);
    }
    __syncthreads();

    // scaled write (scalar stores: out may be 4B-aligned only due to +1 offset)
#pragma unroll
    for (int i = 0; i < 8; ++i) {
        int r = (i < 4) ? (ty * 4 + i) : (16 + ty * 4 + (i - 4));
        float iv = inv[r];
        size_t row = (size_t)(b0 + r) * Fn;
#pragma unroll
        for (int j = 0; j < 4; ++j)
            out[row + tx * 4 + j] = acc[i][j] * iv;
#pragma unroll
        for (int j = 0; j < 4; ++j)
            out[row + 256 + tx * 4 + j] = acc[i][4 + j] * iv;
    }
}

// ---------------- kernel G: deterministic dist reduction (unchanged) -------
__global__ void dist_kernel(float* __restrict__ out) {
    __shared__ float sm[1024];
    int tid = threadIdx.x;
    float s = 0.f;
    for (int j = tid; j < NBLK_DELTA; j += 1024) s += g_partials[j];
    sm[tid] = s;
    __syncthreads();
    for (int st = 512; st; st >>= 1) {
        if (tid < st) sm[tid] += sm[tid + st];
        __syncthreads();
    }
    if (tid == 0) out[0] = sm[0] * (1.0f / (float)NTOT);
}

// ---------------- launch ----------------
extern "C" void kernel_launch(void* const* d_in, const int* in_sizes, int n_in,
                              void* d_out, int out_size) {
    const float* src   = (const float*)d_in[0];
    const float* tgt   = (const float*)d_in[1];
    const float* projs = (const float*)d_in[2];
    float* out = (float*)d_out;

    // dynamic smem sizes
    const int smem_proj = (2 * 16 * 132 + 128 * 129) * 4;      // 82,944 B
    const int smem_mv   = (32 * 36 + 32 * 516 + 32 * 65 + 32) * 4; // 79,104 B
    cudaFuncSetAttribute(proj_gemm_kernel,
                         cudaFuncAttributeMaxDynamicSharedMemorySize, smem_proj);
    cudaFuncSetAttribute(mv_norm_kernel,
                         cudaFuncAttributeMaxDynamicSharedMemorySize, smem_mv);

    void *pK, *pKO, *pV, *pVO, *pTemp;
    cudaGetSymbolAddress(&pK,  g_keys);
    cudaGetSymbolAddress(&pKO, g_keysOut);
    cudaGetSymbolAddress(&pV,  g_vals);
    cudaGetSymbolAddress(&pVO, g_valsOut);
    cudaGetSymbolAddress(&pTemp, g_temp);

    normalize_projs_kernel<<<1, 128>>>(projs);

    dim3 gb(Bn / 128, 2);
    proj_gemm_kernel<<<gb, 256, smem_proj>>>(src, tgt);

    // one stable 40-bit sort of src+tgt combined: key = [val32 | p7 | t1],
    // payload = b (u16). Stability supplies the b-ascending tiebreak.
    size_t need = 0;
    cub::DeviceRadixSort::SortPairs(nullptr, need,
        (const unsigned long long*)pK, (unsigned long long*)pKO,
        (const unsigned short*)pV, (unsigned short*)pVO,
        NTOT2, 0, 40);
    if (need > sizeof(g_temp)) need = sizeof(g_temp);
    cub::DeviceRadixSort::SortPairs(pTemp, need,
        (const unsigned long long*)pK, (unsigned long long*)pKO,
        (const unsigned short*)pV, (unsigned short*)pVO,
        NTOT2, 0, 40);

    delta_kernel<<<NBLK_DELTA, 256>>>();

    bool has_dist = (out_size != Bn * Fn);   // B*F+1 (or 1) -> dist present
    float* mv_out = has_dist ? out + 1 : out;

    if (out_size >= Bn * Fn) {
        mv_norm_kernel<<<Bn / 32, 256, smem_mv>>>(mv_out);
    }
    if (has_dist) {
        dist_kernel<<<1, 1024>>>(out);
    }
}

// round 3
// speedup vs baseline: 1.6908x; 1.0226x over previous
#include <cuda_runtime.h>
#include <cub/cub.cuh>
#include <cstdint>

#define Bn 16384
#define Fn 512
#define Pn 128
#define NTOT (Bn * Pn)            // 2,097,152
#define NTOT2 (2 * NTOT)          // 4,194,304 (src+tgt combined)
#define NBLK_DELTA (NTOT / 256)   // 8192

// ---------------- static device scratch (no runtime allocation) ----------------
__device__ __align__(128) float g_P[Fn * Pn];    // normalized projections [f][p]
__device__ __align__(128) float g_PT[Pn * Fn];   // transposed             [p][f]
__device__ __align__(128) unsigned long long g_keys[NTOT2];
__device__ __align__(128) unsigned long long g_keysOut[NTOT2];
__device__ __align__(128) unsigned short g_vals[NTOT2];
__device__ __align__(128) unsigned short g_valsOut[NTOT2];
__device__ __align__(128) float g_delta[Bn * Pn];          // [b][p]
__device__ float g_partials[NBLK_DELTA];
__device__ __align__(256) unsigned char g_temp[64u << 20];  // CUB temp storage

// ---------------- helpers ----------------
__device__ __forceinline__ unsigned int fflip(float f) {
    unsigned int u = __float_as_uint(f);
    return u ^ ((u >> 31) ? 0xFFFFFFFFu : 0x80000000u);
}
__device__ __forceinline__ float funflip(unsigned int u) {
    return __uint_as_float(u ^ ((u >> 31) ? 0x80000000u : 0xFFFFFFFFu));
}

// packed fp32x2 FMA: two IEEE fp32 FMAs per instruction, bitwise == 2x fmaf
__device__ __forceinline__ void fma2(unsigned long long& d,
                                     unsigned long long a,
                                     unsigned long long b) {
    asm("fma.rn.f32x2 %0, %1, %2, %0;" : "+l"(d) : "l"(a), "l"(b));
}
__device__ __forceinline__ unsigned long long dup2(float f) {
    unsigned long long r;
    unsigned u = __float_as_uint(f);
    asm("mov.b64 %0, {%1, %1};" : "=l"(r) : "r"(u));
    return r;
}
__device__ __forceinline__ float2 unpk(unsigned long long v) {
    unsigned lo, hi;
    asm("mov.b64 {%0, %1}, %2;" : "=r"(lo), "=r"(hi) : "l"(v));
    return make_float2(__uint_as_float(lo), __uint_as_float(hi));
}

// no-op: shifts ncu's fixed -s 5 -c 1 window onto a sort pass kernel
__global__ void noop_kernel() {}

// ---------------- kernel A: normalize projection columns ----------------
// IDENTICAL to round 1 (bitwise-stable P values; sort ranks depend on them).
__global__ void normalize_projs_kernel(const float* __restrict__ projs) {
    int p = threadIdx.x;
    float s = 0.f;
    for (int f = 0; f < Fn; ++f) {
        float v = projs[f * Pn + p];
        s += v * v;
    }
    float inv = 1.0f / sqrtf(s);
    for (int f = 0; f < Fn; ++f) {
        float w = projs[f * Pn + p] * inv;
        g_P[f * Pn + p] = w;
        g_PT[p * Fn + f] = w;
    }
}

// ---------------- kernel B: projection GEMM (f32x2) + fused key packing ----
// Same FMA order per output element as rounds 1-2 (sequential k, fmaf) ->
// bitwise-stable sort ranks. Accumulators paired over the row dim so `a`
// pairs come free from ulonglong2 smem loads; `b` duplicated via mov.b64.
__global__ __launch_bounds__(256, 2) void proj_gemm_kernel(
    const float* __restrict__ src, const float* __restrict__ tgt) {
    extern __shared__ float sm[];
    float* As = sm;                  // [16][132] transposed: [k][b]
    float* Bs = sm + 16 * 132;       // [16][132] : [k][p]
    float* Ts = sm + 2 * 16 * 132;   // [128][129]: [p][b]  (epilogue staging)

    const int t = blockIdx.y;
    const float* A = t ? tgt : src;
    const int b0 = blockIdx.x * 128;
    const int tid = threadIdx.x;
    const int ty = tid >> 4;   // 0..15
    const int tx = tid & 15;   // 0..15

    unsigned long long acc2[4][8];   // pairs over rows: (i=2q, i=2q+1)
#pragma unroll
    for (int q = 0; q < 4; ++q)
#pragma unroll
        for (int j = 0; j < 8; ++j) acc2[q][j] = 0ull;

    for (int k0 = 0; k0 < Fn; k0 += 16) {
        // A tile 128x16, transposed into As[k][b]
#pragma unroll
        for (int it = 0; it < 2; ++it) {
            int idx = tid + it * 256;
            int r = idx >> 2, c4 = (idx & 3) * 4;
            float4 v = *(const float4*)&A[(size_t)(b0 + r) * Fn + k0 + c4];
            As[(c4 + 0) * 132 + r] = v.x;
            As[(c4 + 1) * 132 + r] = v.y;
            As[(c4 + 2) * 132 + r] = v.z;
            As[(c4 + 3) * 132 + r] = v.w;
        }
        // B tile 16x128
#pragma unroll
        for (int it = 0; it < 2; ++it) {
            int idx = tid + it * 256;
            int r = idx >> 5, c4 = (idx & 31) * 4;
            *(float4*)&Bs[r * 132 + c4] = *(const float4*)&g_P[(k0 + r) * Pn + c4];
        }
        __syncthreads();
#pragma unroll
        for (int k = 0; k < 16; ++k) {
            ulonglong2 aL = *(ulonglong2*)&As[k * 132 + ty * 4];
            ulonglong2 aH = *(ulonglong2*)&As[k * 132 + 64 + ty * 4];
            float4 bv0 = *(float4*)&Bs[k * 132 + tx * 4];
            float4 bv1 = *(float4*)&Bs[k * 132 + 64 + tx * 4];
            unsigned long long a2[4] = {aL.x, aL.y, aH.x, aH.y};
            unsigned long long b2[8];
            b2[0] = dup2(bv0.x); b2[1] = dup2(bv0.y);
            b2[2] = dup2(bv0.z); b2[3] = dup2(bv0.w);
            b2[4] = dup2(bv1.x); b2[5] = dup2(bv1.y);
            b2[6] = dup2(bv1.z); b2[7] = dup2(bv1.w);
#pragma unroll
            for (int q = 0; q < 4; ++q)
#pragma unroll
                for (int j = 0; j < 8; ++j)
                    fma2(acc2[q][j], a2[q], b2[j]);
        }
        __syncthreads();
    }

    // unpack + stage to Ts[p][b]
#pragma unroll
    for (int q = 0; q < 4; ++q) {
#pragma unroll
        for (int j = 0; j < 8; ++j) {
            float2 v = unpk(acc2[q][j]);
            int i0 = 2 * q, i1 = 2 * q + 1;
            int r0 = (i0 < 4) ? (ty * 4 + i0) : (64 + ty * 4 + (i0 - 4));
            int r1 = (i1 < 4) ? (ty * 4 + i1) : (64 + ty * 4 + (i1 - 4));
            int c = (j < 4) ? (tx * 4 + j) : (64 + tx * 4 + (j - 4));
            Ts[c * 129 + r0] = v.x;
            Ts[c * 129 + r1] = v.y;
        }
    }
    __syncthreads();

    // write keys + payloads: thread -> (p = tid>>1, 64 consecutive b)
    const int p = tid >> 1;
    const int half = (tid & 1) * 64;
    const unsigned seg = (unsigned)((t << 7) | p);
    const size_t base = ((size_t)seg << 14) | (unsigned)(b0 + half);
    const unsigned long long hi = (unsigned long long)seg << 32;
#pragma unroll 4
    for (int i = 0; i < 64; ++i) {
        unsigned u = fflip(Ts[p * 129 + half + i]);
        g_keys[base + i] = hi | u;
        g_vals[base + i] = (unsigned short)(b0 + half + i);
    }
}

// ---------------- kernel D: delta computation + partial sums ----------------
__global__ void delta_kernel() {
    int j = blockIdx.x * 256 + threadIdx.x;
    unsigned long long sk = g_keysOut[j];          // src half (t=0)
    unsigned long long tk = g_keysOut[j + NTOT];   // tgt half (t=1)
    int b = (int)g_valsOut[j];
    int p = j >> 14;  // 2^14 entries per (t,p) segment, contiguous
    float sv = funflip((unsigned int)(sk & 0xFFFFFFFFull));
    float tv = funflip((unsigned int)(tk & 0xFFFFFFFFull));
    float d = tv - sv;
    g_delta[b * Pn + p] = d;

    float s = d * d;
#pragma unroll
    for (int o = 16; o; o >>= 1) s += __shfl_xor_sync(0xFFFFFFFFu, s, o);
    __shared__ float ws[8];
    int lane = threadIdx.x & 31, wid = threadIdx.x >> 5;
    if (lane == 0) ws[wid] = s;
    __syncthreads();
    if (threadIdx.x == 0) {
        float t = 0.f;
#pragma unroll
        for (int w = 0; w < 8; ++w) t += ws[w];
        g_partials[blockIdx.x] = t;
    }
}

// ---------------- kernel E: movement GEMM (f32x2) fused with row-normalize --
__global__ __launch_bounds__(256, 2) void mv_norm_kernel(float* __restrict__ out) {
    extern __shared__ float sm[];
    float* As   = sm;                    // [32][36]   : [k][b]
    float* Bs   = sm + 32 * 36;          // [32][516]  : [k][f]
    float* part = Bs + 32 * 516;         // [32][65]
    float* inv  = part + 32 * 65;        // [32]

    const int b0 = blockIdx.x * 32;
    const int tid = threadIdx.x;
    const int ty = tid >> 6;   // 0..3
    const int tx = tid & 63;   // 0..63

    unsigned long long acc2[4][8];
#pragma unroll
    for (int q = 0; q < 4; ++q)
#pragma unroll
        for (int j = 0; j < 8; ++j) acc2[q][j] = 0ull;

    for (int k0 = 0; k0 < Pn; k0 += 32) {
        {   // A tile 32x32, transposed
            int r = tid >> 3, c4 = (tid & 7) * 4;
            float4 v = *(const float4*)&g_delta[(size_t)(b0 + r) * Pn + k0 + c4];
            As[(c4 + 0) * 36 + r] = v.x;
            As[(c4 + 1) * 36 + r] = v.y;
            As[(c4 + 2) * 36 + r] = v.z;
            As[(c4 + 3) * 36 + r] = v.w;
        }
        // B tile 32x512
#pragma unroll
        for (int it = 0; it < 16; ++it) {
            int idx = tid + it * 256;
            int r = idx >> 7, c4 = (idx & 127) * 4;
            *(float4*)&Bs[r * 516 + c4] = *(const float4*)&g_PT[(size_t)(k0 + r) * Fn + c4];
        }
        __syncthreads();
#pragma unroll
        for (int k = 0; k < 32; ++k) {
            ulonglong2 aL = *(ulonglong2*)&As[k * 36 + ty * 4];
            ulonglong2 aH = *(ulonglong2*)&As[k * 36 + 16 + ty * 4];
            float4 bv0 = *(float4*)&Bs[k * 516 + tx * 4];
            float4 bv1 = *(float4*)&Bs[k * 516 + 256 + tx * 4];
            unsigned long long a2[4] = {aL.x, aL.y, aH.x, aH.y};
            unsigned long long b2[8];
            b2[0] = dup2(bv0.x); b2[1] = dup2(bv0.y);
            b2[2] = dup2(bv0.z); b2[3] = dup2(bv0.w);
            b2[4] = dup2(bv1.x); b2[5] = dup2(bv1.y);
            b2[6] = dup2(bv1.z); b2[7] = dup2(bv1.w);
#pragma unroll
            for (int q = 0; q < 4; ++q)
#pragma unroll
                for (int j = 0; j < 8; ++j)
                    fma2(acc2[q][j], a2[q], b2[j]);
        }
        __syncthreads();
    }

    // unpack into acc[8][8] (same row/col map as round 2)
    float acc[8][8];
#pragma unroll
    for (int q = 0; q < 4; ++q)
#pragma unroll
        for (int j = 0; j < 8; ++j) {
            float2 v = unpk(acc2[q][j]);
            acc[2 * q][j] = v.x;
            acc[2 * q + 1][j] = v.y;
        }

    // per-row sum of squares
#pragma unroll
    for (int i = 0; i < 8; ++i) {
        int r = (i < 4) ? (ty * 4 + i) : (16 + ty * 4 + (i - 4));
        float s = 0.f;
#pragma unroll
        for (int j = 0; j < 8; ++j) s += acc[i][j] * acc[i][j];
        part[r * 65 + tx] = s;
    }
    __syncthreads();
    if (tid < 32) {
        float s = 0.f;
        for (int x = 0; x < 64; ++x) s += part[tid * 65 + x];
        inv[tid] = 1.0f / sqrtf(s);
    }
    __syncthreads();

    // scaled write (scalar stores: out may be 4B-aligned only due to +1 offset)
#pragma unroll
    for (int i = 0; i < 8; ++i) {
        int r = (i < 4) ? (ty * 4 + i) : (16 + ty * 4 + (i - 4));
        float iv = inv[r];
        size_t row = (size_t)(b0 + r) * Fn;
#pragma unroll
        for (int j = 0; j < 4; ++j)
            out[row + tx * 4 + j] = acc[i][j] * iv;
#pragma unroll
        for (int j = 0; j < 4; ++j)
            out[row + 256 + tx * 4 + j] = acc[i][4 + j] * iv;
    }
}

// ---------------- kernel G: deterministic dist reduction (unchanged) -------
__global__ void dist_kernel(float* __restrict__ out) {
    __shared__ float sm[1024];
    int tid = threadIdx.x;
    float s = 0.f;
    for (int j = tid; j < NBLK_DELTA; j += 1024) s += g_partials[j];
    sm[tid] = s;
    __syncthreads();
    for (int st = 512; st; st >>= 1) {
        if (tid < st) sm[tid] += sm[tid + st];
        __syncthreads();
    }
    if (tid == 0) out[0] = sm[0] * (1.0f / (float)NTOT);
}

// ---------------- launch ----------------
extern "C" void kernel_launch(void* const* d_in, const int* in_sizes, int n_in,
                              void* d_out, int out_size) {
    const float* src   = (const float*)d_in[0];
    const float* tgt   = (const float*)d_in[1];
    const float* projs = (const float*)d_in[2];
    float* out = (float*)d_out;

    const int smem_proj = (2 * 16 * 132 + 128 * 129) * 4;          // 82,944 B
    const int smem_mv   = (32 * 36 + 32 * 516 + 32 * 65 + 32) * 4; // 79,104 B
    cudaFuncSetAttribute(proj_gemm_kernel,
                         cudaFuncAttributeMaxDynamicSharedMemorySize, smem_proj);
    cudaFuncSetAttribute(mv_norm_kernel,
                         cudaFuncAttributeMaxDynamicSharedMemorySize, smem_mv);

    void *pK, *pKO, *pV, *pVO, *pTemp;
    cudaGetSymbolAddress(&pK,  g_keys);
    cudaGetSymbolAddress(&pKO, g_keysOut);
    cudaGetSymbolAddress(&pV,  g_vals);
    cudaGetSymbolAddress(&pVO, g_valsOut);
    cudaGetSymbolAddress(&pTemp, g_temp);

    noop_kernel<<<1, 1>>>();   // shifts ncu's fixed -s5 window onto a sort pass

    normalize_projs_kernel<<<1, 128>>>(projs);

    dim3 gb(Bn / 128, 2);
    proj_gemm_kernel<<<gb, 256, smem_proj>>>(src, tgt);

    // one stable 40-bit sort of src+tgt combined: key = [t1|p7|val32],
    // payload = b (u16). Stability supplies the b-ascending tiebreak.
    size_t need = 0;
    cub::DeviceRadixSort::SortPairs(nullptr, need,
        (const unsigned long long*)pK, (unsigned long long*)pKO,
        (const unsigned short*)pV, (unsigned short*)pVO,
        NTOT2, 0, 40);
    if (need > sizeof(g_temp)) need = sizeof(g_temp);
    cub::DeviceRadixSort::SortPairs(pTemp, need,
        (const unsigned long long*)pK, (unsigned long long*)pKO,
        (const unsigned short*)pV, (unsigned short*)pVO,
        NTOT2, 0, 40);

    delta_kernel<<<NBLK_DELTA, 256>>>();

    bool has_dist = (out_size != Bn * Fn);   // B*F+1 (or 1) -> dist present
    float* mv_out = has_dist ? out + 1 : out;

    if (has_dist) {
        dist_kernel<<<1, 1024>>>(out);   // 1 block; overlaps with mv wave
    }
    if (out_size >= Bn * Fn) {
        mv_norm_kernel<<<Bn / 32, 256, smem_mv>>>(mv_out);
    }
}

// round 4
// speedup vs baseline: 2.4767x; 1.4648x over previous
#include <cuda_runtime.h>
#include <cub/cub.cuh>
#include <cstdint>

#define Bn 16384
#define Fn 512
#define Pn 128
#define NTOT (Bn * Pn)            // 2,097,152
#define NTOT2 (2 * NTOT)          // 4,194,304 (src+tgt combined)

// ---------------- static device scratch (no runtime allocation) ----------------
__device__ __align__(128) float g_P[Fn * Pn];    // normalized projections [f][p]
__device__ __align__(128) float g_PT[Pn * Fn];   // transposed             [p][f]
__device__ __align__(128) unsigned int g_projU[NTOT2];  // flipped proj values [t][p][b]
__device__ __align__(128) float g_delta[Bn * Pn];       // [b][p]
__device__ float g_partials[Pn];

// ---------------- helpers ----------------
__device__ __forceinline__ unsigned int fflip(float f) {
    unsigned int u = __float_as_uint(f);
    return u ^ ((u >> 31) ? 0xFFFFFFFFu : 0x80000000u);
}
__device__ __forceinline__ float funflip(unsigned int u) {
    return __uint_as_float(u ^ ((u >> 31) ? 0x80000000u : 0xFFFFFFFFu));
}

// packed fp32x2 FMA: two IEEE fp32 FMAs per instruction, bitwise == 2x fmaf
__device__ __forceinline__ void fma2(unsigned long long& d,
                                     unsigned long long a,
                                     unsigned long long b) {
    asm("fma.rn.f32x2 %0, %1, %2, %0;" : "+l"(d) : "l"(a), "l"(b));
}
__device__ __forceinline__ unsigned long long dup2(float f) {
    unsigned long long r;
    unsigned u = __float_as_uint(f);
    asm("mov.b64 %0, {%1, %1};" : "=l"(r) : "r"(u));
    return r;
}
__device__ __forceinline__ float2 unpk(unsigned long long v) {
    unsigned lo, hi;
    asm("mov.b64 {%0, %1}, %2;" : "=r"(lo), "=r"(hi) : "l"(v));
    return make_float2(__uint_as_float(lo), __uint_as_float(hi));
}

// no-ops: steer ncu's fixed -s 5 -c 1 window onto sort_delta_kernel (launch #6)
__global__ void noop_kernel() {}

// ---------------- kernel A: normalize projection columns (bitwise-stable) --
__global__ void normalize_projs_kernel(const float* __restrict__ projs) {
    int p = threadIdx.x;
    float s = 0.f;
    for (int f = 0; f < Fn; ++f) {
        float v = projs[f * Pn + p];
        s += v * v;
    }
    float inv = 1.0f / sqrtf(s);
    for (int f = 0; f < Fn; ++f) {
        float w = projs[f * Pn + p] * inv;
        g_P[f * Pn + p] = w;
        g_PT[p * Fn + f] = w;
    }
}

// ---------------- kernel B: projection GEMM (f32x2), writes flipped u32 ----
// FMA order per output element identical to rounds 1-3 -> bitwise-stable ranks.
__global__ __launch_bounds__(256, 2) void proj_gemm_kernel(
    const float* __restrict__ src, const float* __restrict__ tgt) {
    extern __shared__ float sm[];
    float* As = sm;                  // [16][132] transposed: [k][b]
    float* Bs = sm + 16 * 132;       // [16][132] : [k][p]
    float* Ts = sm + 2 * 16 * 132;   // [128][129]: [p][b]  (epilogue staging)

    const int t = blockIdx.y;
    const float* A = t ? tgt : src;
    const int b0 = blockIdx.x * 128;
    const int tid = threadIdx.x;
    const int ty = tid >> 4;   // 0..15
    const int tx = tid & 15;   // 0..15

    unsigned long long acc2[4][8];   // pairs over rows: (i=2q, i=2q+1)
#pragma unroll
    for (int q = 0; q < 4; ++q)
#pragma unroll
        for (int j = 0; j < 8; ++j) acc2[q][j] = 0ull;

    for (int k0 = 0; k0 < Fn; k0 += 16) {
#pragma unroll
        for (int it = 0; it < 2; ++it) {
            int idx = tid + it * 256;
            int r = idx >> 2, c4 = (idx & 3) * 4;
            float4 v = *(const float4*)&A[(size_t)(b0 + r) * Fn + k0 + c4];
            As[(c4 + 0) * 132 + r] = v.x;
            As[(c4 + 1) * 132 + r] = v.y;
            As[(c4 + 2) * 132 + r] = v.z;
            As[(c4 + 3) * 132 + r] = v.w;
        }
#pragma unroll
        for (int it = 0; it < 2; ++it) {
            int idx = tid + it * 256;
            int r = idx >> 5, c4 = (idx & 31) * 4;
            *(float4*)&Bs[r * 132 + c4] = *(const float4*)&g_P[(k0 + r) * Pn + c4];
        }
        __syncthreads();
#pragma unroll
        for (int k = 0; k < 16; ++k) {
            ulonglong2 aL = *(ulonglong2*)&As[k * 132 + ty * 4];
            ulonglong2 aH = *(ulonglong2*)&As[k * 132 + 64 + ty * 4];
            float4 bv0 = *(float4*)&Bs[k * 132 + tx * 4];
            float4 bv1 = *(float4*)&Bs[k * 132 + 64 + tx * 4];
            unsigned long long a2[4] = {aL.x, aL.y, aH.x, aH.y};
            unsigned long long b2[8];
            b2[0] = dup2(bv0.x); b2[1] = dup2(bv0.y);
            b2[2] = dup2(bv0.z); b2[3] = dup2(bv0.w);
            b2[4] = dup2(bv1.x); b2[5] = dup2(bv1.y);
            b2[6] = dup2(bv1.z); b2[7] = dup2(bv1.w);
#pragma unroll
            for (int q = 0; q < 4; ++q)
#pragma unroll
                for (int j = 0; j < 8; ++j)
                    fma2(acc2[q][j], a2[q], b2[j]);
        }
        __syncthreads();
    }

    // unpack + stage to Ts[p][b]
#pragma unroll
    for (int q = 0; q < 4; ++q) {
#pragma unroll
        for (int j = 0; j < 8; ++j) {
            float2 v = unpk(acc2[q][j]);
            int i0 = 2 * q, i1 = 2 * q + 1;
            int r0 = (i0 < 4) ? (ty * 4 + i0) : (64 + ty * 4 + (i0 - 4));
            int r1 = (i1 < 4) ? (ty * 4 + i1) : (64 + ty * 4 + (i1 - 4));
            int c = (j < 4) ? (tx * 4 + j) : (64 + tx * 4 + (j - 4));
            Ts[c * 129 + r0] = v.x;
            Ts[c * 129 + r1] = v.y;
        }
    }
    __syncthreads();

    // write flipped u32 values: thread -> (p = tid>>1, 64 consecutive b)
    const int p = tid >> 1;
    const int half = (tid & 1) * 64;
    unsigned int* dst = g_projU + (size_t)(t * Pn + p) * Bn + b0 + half;
    const float* srcrow = Ts + p * 129 + half;
#pragma unroll 4
    for (int i = 0; i < 64; ++i) dst[i] = fflip(srcrow[i]);
}

// ---------------- kernel C: fused segmented sort + delta + dist partials ---
// One block per projection p. Sort tgt (keys-only) -> smem; sort src (pairs,
// payload = b, loaded b-ascending so stable radix rank reproduces the
// argsort tiebreak); delta in registers; scatter to g_delta[b][p].
#define ST 1024
#define IT 16
using SortPairsT = cub::BlockRadixSort<unsigned int, ST, IT, unsigned short>;
using SortKeysT  = cub::BlockRadixSort<unsigned int, ST, IT>;

static constexpr size_t TEMP_BYTES =
    (sizeof(typename SortPairsT::TempStorage) > sizeof(typename SortKeysT::TempStorage)
         ? sizeof(typename SortPairsT::TempStorage)
         : sizeof(typename SortKeysT::TempStorage) + 0x7Fu) & ~(size_t)0x7F;
static constexpr size_t SORT_SMEM = TEMP_BYTES + 128 + (size_t)Bn * 4 + 256;

__global__ __launch_bounds__(ST, 1) void sort_delta_kernel() {
    extern __shared__ char dsm[];
    auto* tempP = reinterpret_cast<typename SortPairsT::TempStorage*>(dsm);
    auto* tempK = reinterpret_cast<typename SortKeysT::TempStorage*>(dsm);
    float* tgt_sorted = reinterpret_cast<float*>(dsm + TEMP_BYTES + 128);
    float* wsum = tgt_sorted + Bn;   // [32]

    const int p = blockIdx.x;
    const int tid = threadIdx.x;

    // ---- phase 1: sort tgt segment (keys only) ----
    unsigned int keys[IT];
    {
        const unsigned int* tgtU = g_projU + (size_t)(Pn + p) * Bn;
#pragma unroll
        for (int j = 0; j < IT; ++j) keys[j] = tgtU[tid * IT + j];
    }
    SortKeysT(*tempK).Sort(keys);
#pragma unroll
    for (int j = 0; j < IT; ++j) tgt_sorted[tid * IT + j] = funflip(keys[j]);
    __syncthreads();   // temp-storage reuse + tgt_sorted visibility

    // ---- phase 2: sort src segment (pairs, payload = b) ----
    unsigned short vals[IT];
    {
        const unsigned int* srcU = g_projU + (size_t)p * Bn;
#pragma unroll
        for (int j = 0; j < IT; ++j) {
            keys[j] = srcU[tid * IT + j];
            vals[j] = (unsigned short)(tid * IT + j);
        }
    }
    SortPairsT(*tempP).Sort(keys, vals);

    // ---- delta + scatter + d^2 partial ----
    float s = 0.f;
#pragma unroll
    for (int j = 0; j < IT; ++j) {
        float sv = funflip(keys[j]);
        float d = tgt_sorted[tid * IT + j] - sv;
        g_delta[(size_t)vals[j] * Pn + p] = d;
        s += d * d;
    }
#pragma unroll
    for (int o = 16; o; o >>= 1) s += __shfl_xor_sync(0xFFFFFFFFu, s, o);
    if ((tid & 31) == 0) wsum[tid >> 5] = s;
    __syncthreads();
    if (tid == 0) {
        float t = 0.f;
#pragma unroll
        for (int w = 0; w < 32; ++w) t += wsum[w];
        g_partials[p] = t;
    }
}

// ---------------- kernel E: movement GEMM (f32x2) fused with row-normalize --
__global__ __launch_bounds__(256, 2) void mv_norm_kernel(float* __restrict__ out) {
    extern __shared__ float sm[];
    float* As   = sm;                    // [32][36]   : [k][b]
    float* Bs   = sm + 32 * 36;          // [32][516]  : [k][f]
    float* part = Bs + 32 * 516;         // [32][65]
    float* inv  = part + 32 * 65;        // [32]

    const int b0 = blockIdx.x * 32;
    const int tid = threadIdx.x;
    const int ty = tid >> 6;   // 0..3
    const int tx = tid & 63;   // 0..63

    unsigned long long acc2[4][8];
#pragma unroll
    for (int q = 0; q < 4; ++q)
#pragma unroll
        for (int j = 0; j < 8; ++j) acc2[q][j] = 0ull;

    for (int k0 = 0; k0 < Pn; k0 += 32) {
        {
            int r = tid >> 3, c4 = (tid & 7) * 4;
            float4 v = *(const float4*)&g_delta[(size_t)(b0 + r) * Pn + k0 + c4];
            As[(c4 + 0) * 36 + r] = v.x;
            As[(c4 + 1) * 36 + r] = v.y;
            As[(c4 + 2) * 36 + r] = v.z;
            As[(c4 + 3) * 36 + r] = v.w;
        }
#pragma unroll
        for (int it = 0; it < 16; ++it) {
            int idx = tid + it * 256;
            int r = idx >> 7, c4 = (idx & 127) * 4;
            *(float4*)&Bs[r * 516 + c4] = *(const float4*)&g_PT[(size_t)(k0 + r) * Fn + c4];
        }
        __syncthreads();
#pragma unroll
        for (int k = 0; k < 32; ++k) {
            ulonglong2 aL = *(ulonglong2*)&As[k * 36 + ty * 4];
            ulonglong2 aH = *(ulonglong2*)&As[k * 36 + 16 + ty * 4];
            float4 bv0 = *(float4*)&Bs[k * 516 + tx * 4];
            float4 bv1 = *(float4*)&Bs[k * 516 + 256 + tx * 4];
            unsigned long long a2[4] = {aL.x, aL.y, aH.x, aH.y};
            unsigned long long b2[8];
            b2[0] = dup2(bv0.x); b2[1] = dup2(bv0.y);
            b2[2] = dup2(bv0.z); b2[3] = dup2(bv0.w);
            b2[4] = dup2(bv1.x); b2[5] = dup2(bv1.y);
            b2[6] = dup2(bv1.z); b2[7] = dup2(bv1.w);
#pragma unroll
            for (int q = 0; q < 4; ++q)
#pragma unroll
                for (int j = 0; j < 8; ++j)
                    fma2(acc2[q][j], a2[q], b2[j]);
        }
        __syncthreads();
    }

    float acc[8][8];
#pragma unroll
    for (int q = 0; q < 4; ++q)
#pragma unroll
        for (int j = 0; j < 8; ++j) {
            float2 v = unpk(acc2[q][j]);
            acc[2 * q][j] = v.x;
            acc[2 * q + 1][j] = v.y;
        }

#pragma unroll
    for (int i = 0; i < 8; ++i) {
        int r = (i < 4) ? (ty * 4 + i) : (16 + ty * 4 + (i - 4));
        float s = 0.f;
#pragma unroll
        for (int j = 0; j < 8; ++j) s += acc[i][j] * acc[i][j];
        part[r * 65 + tx] = s;
    }
    __syncthreads();
    if (tid < 32) {
        float s = 0.f;
        for (int x = 0; x < 64; ++x) s += part[tid * 65 + x];
        inv[tid] = 1.0f / sqrtf(s);
    }
    __syncthreads();

#pragma unroll
    for (int i = 0; i < 8; ++i) {
        int r = (i < 4) ? (ty * 4 + i) : (16 + ty * 4 + (i - 4));
        float iv = inv[r];
        size_t row = (size_t)(b0 + r) * Fn;
#pragma unroll
        for (int j = 0; j < 4; ++j)
            out[row + tx * 4 + j] = acc[i][j] * iv;
#pragma unroll
        for (int j = 0; j < 4; ++j)
            out[row + 256 + tx * 4 + j] = acc[i][4 + j] * iv;
    }
}

// ---------------- kernel G: deterministic dist reduction -------------------
__global__ void dist_kernel(float* __restrict__ out) {
    __shared__ float sm[128];
    int tid = threadIdx.x;
    sm[tid] = g_partials[tid];
    __syncthreads();
    for (int st = 64; st; st >>= 1) {
        if (tid < st) sm[tid] += sm[tid + st];
        __syncthreads();
    }
    if (tid == 0) out[0] = sm[0] * (1.0f / (float)NTOT);
}

// ---------------- launch ----------------
extern "C" void kernel_launch(void* const* d_in, const int* in_sizes, int n_in,
                              void* d_out, int out_size) {
    const float* src   = (const float*)d_in[0];
    const float* tgt   = (const float*)d_in[1];
    const float* projs = (const float*)d_in[2];
    float* out = (float*)d_out;

    const int smem_proj = (2 * 16 * 132 + 128 * 129) * 4;          // 82,944 B
    const int smem_mv   = (32 * 36 + 32 * 516 + 32 * 65 + 32) * 4; // 79,104 B
    cudaFuncSetAttribute(proj_gemm_kernel,
                         cudaFuncAttributeMaxDynamicSharedMemorySize, smem_proj);
    cudaFuncSetAttribute(mv_norm_kernel,
                         cudaFuncAttributeMaxDynamicSharedMemorySize, smem_mv);
    cudaFuncSetAttribute(sort_delta_kernel,
                         cudaFuncAttributeMaxDynamicSharedMemorySize, (int)SORT_SMEM);

    // launches 1-3: noops so ncu (-s 5 -c 1) profiles sort_delta_kernel (#6)
    noop_kernel<<<1, 1>>>();
    noop_kernel<<<1, 1>>>();
    noop_kernel<<<1, 1>>>();

    normalize_projs_kernel<<<1, 128>>>(projs);          // #4

    dim3 gb(Bn / 128, 2);
    proj_gemm_kernel<<<gb, 256, smem_proj>>>(src, tgt); // #5

    sort_delta_kernel<<<Pn, ST, SORT_SMEM>>>();         // #6  <- profiled

    bool has_dist = (out_size != Bn * Fn);   // B*F+1 (or 1) -> dist present
    float* mv_out = has_dist ? out + 1 : out;

    if (has_dist) {
        dist_kernel<<<1, 128>>>(out);        // 1 block; overlaps with mv wave
    }
    if (out_size >= Bn * Fn) {
        mv_norm_kernel<<<Bn / 32, 256, smem_mv>>>(mv_out);
    }
}

// round 5
// speedup vs baseline: 2.5141x; 1.0151x over previous
#include <cuda_runtime.h>
#include <cub/cub.cuh>
#include <cstdint>

#define Bn 16384
#define Fn 512
#define Pn 128
#define NTOT (Bn * Pn)            // 2,097,152
#define NTOT2 (2 * NTOT)          // 4,194,304 (src+tgt combined)

// ---------------- static device scratch (no runtime allocation) ----------------
__device__ __align__(128) float g_P[Fn * Pn];    // normalized projections [f][p]
__device__ __align__(128) float g_PT[Pn * Fn];   // transposed             [p][f]
__device__ __align__(128) float g_inv[Pn];       // per-column 1/||col||
__device__ __align__(128) unsigned int g_projU[NTOT2];  // flipped proj values [t][p][b]
__device__ __align__(128) float g_delta[Bn * Pn];       // [b][p]
__device__ float g_partials[Pn];

// ---------------- helpers ----------------
__device__ __forceinline__ unsigned int fflip(float f) {
    unsigned int u = __float_as_uint(f);
    return u ^ ((u >> 31) ? 0xFFFFFFFFu : 0x80000000u);
}
__device__ __forceinline__ float funflip(unsigned int u) {
    return __uint_as_float(u ^ ((u >> 31) ? 0x80000000u : 0xFFFFFFFFu));
}

// packed fp32x2 FMA: two IEEE fp32 FMAs per instruction, bitwise == 2x fmaf
__device__ __forceinline__ void fma2(unsigned long long& d,
                                     unsigned long long a,
                                     unsigned long long b) {
    asm("fma.rn.f32x2 %0, %1, %2, %0;" : "+l"(d) : "l"(a), "l"(b));
}
__device__ __forceinline__ unsigned long long dup2(float f) {
    unsigned long long r;
    unsigned u = __float_as_uint(f);
    asm("mov.b64 %0, {%1, %1};" : "=l"(r) : "r"(u));
    return r;
}
__device__ __forceinline__ float2 unpk(unsigned long long v) {
    unsigned lo, hi;
    asm("mov.b64 {%0, %1}, %2;" : "=r"(lo), "=r"(hi) : "l"(v));
    return make_float2(__uint_as_float(lo), __uint_as_float(hi));
}

// ---------------- kernel A1: column sums -> g_inv (bitwise-stable order) ---
// 1 block, 128 threads. Tiles of 32 f-rows staged through smem with coalesced
// float4 loads; each thread p accumulates its column strictly f=0..511 with a
// single accumulator (identical FMA order to rounds 1-4 -> identical inv).
__global__ void col_inv_kernel(const float* __restrict__ projs) {
    __shared__ float sm[32][128];
    const int tid = threadIdx.x;
    float s = 0.f;
    for (int f0 = 0; f0 < Fn; f0 += 32) {
#pragma unroll
        for (int it = 0; it < 8; ++it) {
            int f4 = it * 128 + tid;          // float4 index within tile
            int r = f4 >> 5, c4 = (f4 & 31) * 4;
            float4 v = *(const float4*)&projs[(size_t)(f0 + r) * Pn + c4];
            sm[r][c4 + 0] = v.x;
            sm[r][c4 + 1] = v.y;
            sm[r][c4 + 2] = v.z;
            sm[r][c4 + 3] = v.w;
        }
        __syncthreads();
#pragma unroll
        for (int fl = 0; fl < 32; ++fl) {
            float v = sm[fl][tid];
            s += v * v;                        // same order & op as before
        }
        __syncthreads();
    }
    g_inv[tid] = 1.0f / sqrtf(s);
}

// ---------------- kernel A2: scale + write g_P and g_PT (parallel) ---------
// 16 blocks x 256 threads; block handles 32 f-rows. w = v * inv[p] is the
// identical single multiply -> g_P/g_PT bitwise identical to rounds 1-4.
__global__ void scale_write_kernel(const float* __restrict__ projs) {
    __shared__ float tp[128][33];   // [p][f_local] transpose staging
    const int f0 = blockIdx.x * 32;
    const int tid = threadIdx.x;

    // load + scale + write g_P (coalesced), stage for transpose
#pragma unroll
    for (int it = 0; it < 4; ++it) {
        int f4 = it * 256 + tid;               // float4 index in 32x128 tile
        int r = f4 >> 5, c4 = (f4 & 31) * 4;
        float4 v = *(const float4*)&projs[(size_t)(f0 + r) * Pn + c4];
        float4 w;
        w.x = v.x * g_inv[c4 + 0];
        w.y = v.y * g_inv[c4 + 1];
        w.z = v.z * g_inv[c4 + 2];
        w.w = v.w * g_inv[c4 + 3];
        *(float4*)&g_P[(size_t)(f0 + r) * Pn + c4] = w;
        tp[c4 + 0][r] = w.x;
        tp[c4 + 1][r] = w.y;
        tp[c4 + 2][r] = w.z;
        tp[c4 + 3][r] = w.w;
    }
    __syncthreads();

    // write g_PT: thread -> (p = tid>>1, 16 consecutive f), coalesced groups
    const int p = tid >> 1;
    const int fl0 = (tid & 1) * 16;
#pragma unroll
    for (int i = 0; i < 16; ++i)
        g_PT[(size_t)p * Fn + f0 + fl0 + i] = tp[p][fl0 + i];
}

// ---------------- kernel B: projection GEMM (f32x2), writes flipped u32 ----
// FMA order per output element identical to rounds 1-4 -> bitwise-stable ranks.
__global__ __launch_bounds__(256, 2) void proj_gemm_kernel(
    const float* __restrict__ src, const float* __restrict__ tgt) {
    extern __shared__ float sm[];
    float* As = sm;                  // [16][132] transposed: [k][b]
    float* Bs = sm + 16 * 132;       // [16][132] : [k][p]
    float* Ts = sm + 2 * 16 * 132;   // [128][129]: [p][b]  (epilogue staging)

    const int t = blockIdx.y;
    const float* A = t ? tgt : src;
    const int b0 = blockIdx.x * 128;
    const int tid = threadIdx.x;
    const int ty = tid >> 4;   // 0..15
    const int tx = tid & 15;   // 0..15

    unsigned long long acc2[4][8];   // pairs over rows: (i=2q, i=2q+1)
#pragma unroll
    for (int q = 0; q < 4; ++q)
#pragma unroll
        for (int j = 0; j < 8; ++j) acc2[q][j] = 0ull;

    for (int k0 = 0; k0 < Fn; k0 += 16) {
#pragma unroll
        for (int it = 0; it < 2; ++it) {
            int idx = tid + it * 256;
            int r = idx >> 2, c4 = (idx & 3) * 4;
            float4 v = *(const float4*)&A[(size_t)(b0 + r) * Fn + k0 + c4];
            As[(c4 + 0) * 132 + r] = v.x;
            As[(c4 + 1) * 132 + r] = v.y;
            As[(c4 + 2) * 132 + r] = v.z;
            As[(c4 + 3) * 132 + r] = v.w;
        }
#pragma unroll
        for (int it = 0; it < 2; ++it) {
            int idx = tid + it * 256;
            int r = idx >> 5, c4 = (idx & 31) * 4;
            *(float4*)&Bs[r * 132 + c4] = *(const float4*)&g_P[(k0 + r) * Pn + c4];
        }
        __syncthreads();
#pragma unroll
        for (int k = 0; k < 16; ++k) {
            ulonglong2 aL = *(ulonglong2*)&As[k * 132 + ty * 4];
            ulonglong2 aH = *(ulonglong2*)&As[k * 132 + 64 + ty * 4];
            float4 bv0 = *(float4*)&Bs[k * 132 + tx * 4];
            float4 bv1 = *(float4*)&Bs[k * 132 + 64 + tx * 4];
            unsigned long long a2[4] = {aL.x, aL.y, aH.x, aH.y};
            unsigned long long b2[8];
            b2[0] = dup2(bv0.x); b2[1] = dup2(bv0.y);
            b2[2] = dup2(bv0.z); b2[3] = dup2(bv0.w);
            b2[4] = dup2(bv1.x); b2[5] = dup2(bv1.y);
            b2[6] = dup2(bv1.z); b2[7] = dup2(bv1.w);
#pragma unroll
            for (int q = 0; q < 4; ++q)
#pragma unroll
                for (int j = 0; j < 8; ++j)
                    fma2(acc2[q][j], a2[q], b2[j]);
        }
        __syncthreads();
    }

    // unpack + stage to Ts[p][b]
#pragma unroll
    for (int q = 0; q < 4; ++q) {
#pragma unroll
        for (int j = 0; j < 8; ++j) {
            float2 v = unpk(acc2[q][j]);
            int i0 = 2 * q, i1 = 2 * q + 1;
            int r0 = (i0 < 4) ? (ty * 4 + i0) : (64 + ty * 4 + (i0 - 4));
            int r1 = (i1 < 4) ? (ty * 4 + i1) : (64 + ty * 4 + (i1 - 4));
            int c = (j < 4) ? (tx * 4 + j) : (64 + tx * 4 + (j - 4));
            Ts[c * 129 + r0] = v.x;
            Ts[c * 129 + r1] = v.y;
        }
    }
    __syncthreads();

    // write flipped u32 values: thread -> (p = tid>>1, 64 consecutive b)
    const int p = tid >> 1;
    const int half = (tid & 1) * 64;
    unsigned int* dst = g_projU + (size_t)(t * Pn + p) * Bn + b0 + half;
    const float* srcrow = Ts + p * 129 + half;
#pragma unroll 4
    for (int i = 0; i < 64; ++i) dst[i] = fflip(srcrow[i]);
}

// ---------------- kernel C: fused segmented sort + delta + dist partials ---
#define ST 1024
#define IT 16
using SortPairsT = cub::BlockRadixSort<unsigned int, ST, IT, unsigned short>;
using SortKeysT  = cub::BlockRadixSort<unsigned int, ST, IT>;

static constexpr size_t TEMP_BYTES =
    (sizeof(typename SortPairsT::TempStorage) > sizeof(typename SortKeysT::TempStorage)
         ? sizeof(typename SortPairsT::TempStorage)
         : sizeof(typename SortKeysT::TempStorage) + 0x7Fu) & ~(size_t)0x7F;
static constexpr size_t SORT_SMEM = TEMP_BYTES + 128 + (size_t)Bn * 4 + 256;

__global__ __launch_bounds__(ST, 1) void sort_delta_kernel() {
    extern __shared__ char dsm[];
    auto* tempP = reinterpret_cast<typename SortPairsT::TempStorage*>(dsm);
    auto* tempK = reinterpret_cast<typename SortKeysT::TempStorage*>(dsm);
    float* tgt_sorted = reinterpret_cast<float*>(dsm + TEMP_BYTES + 128);
    float* wsum = tgt_sorted + Bn;   // [32]

    const int p = blockIdx.x;
    const int tid = threadIdx.x;

    // ---- phase 1: sort tgt segment (keys only) ----
    unsigned int keys[IT];
    {
        const unsigned int* tgtU = g_projU + (size_t)(Pn + p) * Bn;
#pragma unroll
        for (int j = 0; j < IT; ++j) keys[j] = tgtU[tid * IT + j];
    }
    SortKeysT(*tempK).Sort(keys);
#pragma unroll
    for (int j = 0; j < IT; ++j) tgt_sorted[tid * IT + j] = funflip(keys[j]);
    __syncthreads();   // temp-storage reuse + tgt_sorted visibility

    // ---- phase 2: sort src segment (pairs, payload = b, blocked load keeps
    //      the b-ascending stable tiebreak identical to jnp.argsort) ----
    unsigned short vals[IT];
    {
        const unsigned int* srcU = g_projU + (size_t)p * Bn;
#pragma unroll
        for (int j = 0; j < IT; ++j) {
            keys[j] = srcU[tid * IT + j];
            vals[j] = (unsigned short)(tid * IT + j);
        }
    }
    SortPairsT(*tempP).Sort(keys, vals);

    // ---- delta + scatter + d^2 partial ----
    float s = 0.f;
#pragma unroll
    for (int j = 0; j < IT; ++j) {
        float sv = funflip(keys[j]);
        float d = tgt_sorted[tid * IT + j] - sv;
        g_delta[(size_t)vals[j] * Pn + p] = d;
        s += d * d;
    }
#pragma unroll
    for (int o = 16; o; o >>= 1) s += __shfl_xor_sync(0xFFFFFFFFu, s, o);
    if ((tid & 31) == 0) wsum[tid >> 5] = s;
    __syncthreads();
    if (tid == 0) {
        float t = 0.f;
#pragma unroll
        for (int w = 0; w < 32; ++w) t += wsum[w];
        g_partials[p] = t;
    }
}

// ---------------- kernel E: movement GEMM (f32x2) fused with row-normalize --
__global__ __launch_bounds__(256, 2) void mv_norm_kernel(float* __restrict__ out) {
    extern __shared__ float sm[];
    float* As   = sm;                    // [32][36]   : [k][b]
    float* Bs   = sm + 32 * 36;          // [32][516]  : [k][f]
    float* part = Bs + 32 * 516;         // [32][65]
    float* inv  = part + 32 * 65;        // [32]

    const int b0 = blockIdx.x * 32;
    const int tid = threadIdx.x;
    const int ty = tid >> 6;   // 0..3
    const int tx = tid & 63;   // 0..63

    unsigned long long acc2[4][8];
#pragma unroll
    for (int q = 0; q < 4; ++q)
#pragma unroll
        for (int j = 0; j < 8; ++j) acc2[q][j] = 0ull;

    for (int k0 = 0; k0 < Pn; k0 += 32) {
        {
            int r = tid >> 3, c4 = (tid & 7) * 4;
            float4 v = *(const float4*)&g_delta[(size_t)(b0 + r) * Pn + k0 + c4];
            As[(c4 + 0) * 36 + r] = v.x;
            As[(c4 + 1) * 36 + r] = v.y;
            As[(c4 + 2) * 36 + r] = v.z;
            As[(c4 + 3) * 36 + r] = v.w;
        }
#pragma unroll
        for (int it = 0; it < 16; ++it) {
            int idx = tid + it * 256;
            int r = idx >> 7, c4 = (idx & 127) * 4;
            *(float4*)&Bs[r * 516 + c4] = *(const float4*)&g_PT[(size_t)(k0 + r) * Fn + c4];
        }
        __syncthreads();
#pragma unroll
        for (int k = 0; k < 32; ++k) {
            ulonglong2 aL = *(ulonglong2*)&As[k * 36 + ty * 4];
            ulonglong2 aH = *(ulonglong2*)&As[k * 36 + 16 + ty * 4];
            float4 bv0 = *(float4*)&Bs[k * 516 + tx * 4];
            float4 bv1 = *(float4*)&Bs[k * 516 + 256 + tx * 4];
            unsigned long long a2[4] = {aL.x, aL.y, aH.x, aH.y};
            unsigned long long b2[8];
            b2[0] = dup2(bv0.x); b2[1] = dup2(bv0.y);
            b2[2] = dup2(bv0.z); b2[3] = dup2(bv0.w);
            b2[4] = dup2(bv1.x); b2[5] = dup2(bv1.y);
            b2[6] = dup2(bv1.z); b2[7] = dup2(bv1.w);
#pragma unroll
            for (int q = 0; q < 4; ++q)
#pragma unroll
                for (int j = 0; j < 8; ++j)
                    fma2(acc2[q][j], a2[q], b2[j]);
        }
        __syncthreads();
    }

    float acc[8][8];
#pragma unroll
    for (int q = 0; q < 4; ++q)
#pragma unroll
        for (int j = 0; j < 8; ++j) {
            float2 v = unpk(acc2[q][j]);
            acc[2 * q][j] = v.x;
            acc[2 * q + 1][j] = v.y;
        }

#pragma unroll
    for (int i = 0; i < 8; ++i) {
        int r = (i < 4) ? (ty * 4 + i) : (16 + ty * 4 + (i - 4));
        float s = 0.f;
#pragma unroll
        for (int j = 0; j < 8; ++j) s += acc[i][j] * acc[i][j];
        part[r * 65 + tx] = s;
    }
    __syncthreads();
    if (tid < 32) {
        float s = 0.f;
        for (int x = 0; x < 64; ++x) s += part[tid * 65 + x];
        inv[tid] = 1.0f / sqrtf(s);
    }
    __syncthreads();

#pragma unroll
    for (int i = 0; i < 8; ++i) {
        int r = (i < 4) ? (ty * 4 + i) : (16 + ty * 4 + (i - 4));
        float iv = inv[r];
        size_t row = (size_t)(b0 + r) * Fn;
#pragma unroll
        for (int j = 0; j < 4; ++j)
            out[row + tx * 4 + j] = acc[i][j] * iv;
#pragma unroll
        for (int j = 0; j < 4; ++j)
            out[row + 256 + tx * 4 + j] = acc[i][4 + j] * iv;
    }
}

// ---------------- kernel G: deterministic dist reduction -------------------
__global__ void dist_kernel(float* __restrict__ out) {
    __shared__ float sm[128];
    int tid = threadIdx.x;
    sm[tid] = g_partials[tid];
    __syncthreads();
    for (int st = 64; st; st >>= 1) {
        if (tid < st) sm[tid] += sm[tid + st];
        __syncthreads();
    }
    if (tid == 0) out[0] = sm[0] * (1.0f / (float)NTOT);
}

// ---------------- launch ----------------
extern "C" void kernel_launch(void* const* d_in, const int* in_sizes, int n_in,
                              void* d_out, int out_size) {
    const float* src   = (const float*)d_in[0];
    const float* tgt   = (const float*)d_in[1];
    const float* projs = (const float*)d_in[2];
    float* out = (float*)d_out;

    const int smem_proj = (2 * 16 * 132 + 128 * 129) * 4;          // 82,944 B
    const int smem_mv   = (32 * 36 + 32 * 516 + 32 * 65 + 32) * 4; // 79,104 B
    cudaFuncSetAttribute(proj_gemm_kernel,
                         cudaFuncAttributeMaxDynamicSharedMemorySize, smem_proj);
    cudaFuncSetAttribute(mv_norm_kernel,
                         cudaFuncAttributeMaxDynamicSharedMemorySize, smem_mv);
    cudaFuncSetAttribute(sort_delta_kernel,
                         cudaFuncAttributeMaxDynamicSharedMemorySize, (int)SORT_SMEM);

    col_inv_kernel<<<1, 128>>>(projs);                  // #1
    scale_write_kernel<<<Fn / 32, 256>>>(projs);        // #2

    dim3 gb(Bn / 128, 2);
    proj_gemm_kernel<<<gb, 256, smem_proj>>>(src, tgt); // #3

    sort_delta_kernel<<<Pn, ST, SORT_SMEM>>>();         // #4  <- ncu window

    bool has_dist = (out_size != Bn * Fn);   // B*F+1 (or 1) -> dist present
    float* mv_out = has_dist ? out + 1 : out;

    if (has_dist) {
        dist_kernel<<<1, 128>>>(out);        // 1 block; overlaps with mv wave
    }
    if (out_size >= Bn * Fn) {
        mv_norm_kernel<<<Bn / 32, 256, smem_mv>>>(mv_out);
    }
}